// round 4
// baseline (speedup 1.0000x reference)
#include <cuda_runtime.h>
#include <cuda_fp16.h>

#define NODELEN 10
#define DEG 32
#define MAXN 200000
#define PADH 16   // halves per row: 32B = one sector, sector-aligned

// Allocation-free scratch: fp16 gather tables, one sector per row.
__device__ __half g_featH[(size_t)MAXN * PADH];
__device__ __half g_h1H[(size_t)MAXN * PADH];

// ---------------------------------------------------------------------------
// Pack: features [N,10] fp32 -> g_featH [N,16] fp16 (zero padded).
// ---------------------------------------------------------------------------
__global__ __launch_bounds__(256) void pack_features_kernel(
    const float* __restrict__ features, int N)
{
    int idx = blockIdx.x * blockDim.x + threadIdx.x;
    if (idx >= N * PADH) return;
    int n = idx >> 4;
    int k = idx & 15;
    float v = (k < NODELEN) ? features[(size_t)n * NODELEN + k] : 0.f;
    g_featH[idx] = __float2half_rn(v);
}

// ---------------------------------------------------------------------------
// Gather-mean core: one warp per node. Each gathered row = 16 halves = 32B =
// ONE sector. Lane l: r=l>>3 (row-in-group), j=l&7 (dim pair). 8 LDG.32 per
// node, 4 random rows per instruction. Butterfly-reduce over r.
// Returns: lanes 0..7 hold the 32-row SUM for dims (2j, 2j+1) in float2.
// ---------------------------------------------------------------------------
__device__ __forceinline__ float2 gather_sum16(const __half* __restrict__ tab,
                                               int myNb, int lane)
{
    int r = lane >> 3;   // 0..3
    int j = lane & 7;    // dim pair 0..7
    float2 acc = make_float2(0.f, 0.f);
#pragma unroll
    for (int i = 0; i < 8; i++) {
        int nb = __shfl_sync(0xffffffffu, myNb, 4 * i + r);
        __half2 h = *reinterpret_cast<const __half2*>(tab + (size_t)nb * PADH + 2 * j);
        float2 v = __half22float2(h);
        acc.x += v.x; acc.y += v.y;
    }
#pragma unroll
    for (int off = 8; off < 32; off <<= 1) {
        acc.x += __shfl_xor_sync(0xffffffffu, acc.x, off);
        acc.y += __shfl_xor_sync(0xffffffffu, acc.y, off);
    }
    return acc;
}

// ---------------------------------------------------------------------------
// Hop 1: h1 = mean(features[adj]), col 0 zeroed, stored fp16 padded.
// ---------------------------------------------------------------------------
__global__ __launch_bounds__(256) void hop1_kernel(
    const int* __restrict__ adj, int N)
{
    int warp = (blockIdx.x * blockDim.x + threadIdx.x) >> 5;
    int lane = threadIdx.x & 31;
    if (warp >= N) return;

    int myNb = adj[warp * DEG + lane];
    float2 s = gather_sum16(g_featH, myNb, lane);

    if (lane < 8) {
        float2 v;
        v.x = s.x * (1.f / 32.f);
        v.y = s.y * (1.f / 32.f);
        if (lane == 0) v.x = 0.f;            // h1[:,0] = 0
        __half2 h = __floats2half2_rn(v.x, v.y);
        *reinterpret_cast<__half2*>(g_h1H + (size_t)warp * PADH + 2 * lane) = h;
    }
}

// ---------------------------------------------------------------------------
// Hop 2 + emb: agg = mean(h1[adj]) (col0 zero);
// emb = [features fp32 (col0=0) | agg], written fp32 to d_out.
// ---------------------------------------------------------------------------
__global__ __launch_bounds__(256) void hop2_emb_kernel(
    const float* __restrict__ features, const int* __restrict__ adj,
    float* __restrict__ emb, int N)
{
    int warp = (blockIdx.x * blockDim.x + threadIdx.x) >> 5;
    int lane = threadIdx.x & 31;
    if (warp >= N) return;

    int myNb = adj[warp * DEG + lane];
    float2 s = gather_sum16(g_h1H, myNb, lane);

    float* row = emb + (size_t)warp * (2 * NODELEN);
    if (lane < 8) {
        // agg dims (2*lane, 2*lane+1) -> emb cols 10+2*lane (only lane<5 real)
        if (lane < 5) {
            float2 v;
            v.x = s.x * (1.f / 32.f);
            v.y = s.y * (1.f / 32.f);
            if (lane == 0) v.x = 0.f;        // emb[:,NODELEN] = 0
            *reinterpret_cast<float2*>(row + 10 + 2 * lane) = v;
        }
    } else if (lane < 8 + NODELEN) {
        // self features cols 0..9, col 0 zeroed (exact fp32 from input)
        int d = lane - 8;
        row[d] = (d == 0) ? 0.f : features[(size_t)warp * NODELEN + d];
    }
}

// ---------------------------------------------------------------------------
// MLP autoencoder: thread-per-node, weights in shared; emb tile and decoded
// tile staged through shared memory for fully coalesced global traffic.
// ---------------------------------------------------------------------------
#define MLP_BLK 256
#define EMB_PAD 21   // 20-float row padded to 21 (odd -> conflict-free LDS)

__global__ __launch_bounds__(MLP_BLK) void mlp_kernel(
    const float* __restrict__ emb,
    const float* __restrict__ We1, const float* __restrict__ be1,
    const float* __restrict__ We2, const float* __restrict__ be2,
    const float* __restrict__ We3, const float* __restrict__ be3,
    const float* __restrict__ Wd1, const float* __restrict__ bd1,
    const float* __restrict__ Wd2, const float* __restrict__ bd2,
    const float* __restrict__ Wd3, const float* __restrict__ bd3,
    float* __restrict__ enc_out, float* __restrict__ dec_out, int N)
{
    // weight layout (W blocks at 16B-aligned offsets)
    __shared__ float sw[1084];
    __shared__ float se[MLP_BLK * EMB_PAD];

    const int tid = threadIdx.x;
    {
        const float* srcs[12] = {We1, We2, We3, Wd1, Wd2, Wd3,
                                 be1, be2, be3, bd1, bd2, bd3};
        const int off[12] = {0, 300, 452, 504, 556, 708,
                             1008, 1023, 1033, 1038, 1048, 1063};
        const int sz[12]  = {300, 150, 50, 50, 150, 300,
                             15, 10, 5, 10, 15, 20};
#pragma unroll
        for (int a = 0; a < 12; a++)
            for (int k = tid; k < sz[a]; k += MLP_BLK)
                sw[off[a] + k] = srcs[a][k];
    }

    // stage emb tile: coalesced float4 loads (rows are 20 floats, 20%4==0)
    const int base = blockIdx.x * MLP_BLK;          // first node of tile
    const long f4base = (long)base * 5;             // float4 index of tile start
    const long f4total = (long)N * 5;
#pragma unroll
    for (int i = 0; i < 5; i++) {
        long f4 = f4base + tid + i * MLP_BLK;
        if (f4 < f4total) {
            float4 t = reinterpret_cast<const float4*>(emb)[f4];
            int lf4 = tid + i * MLP_BLK;            // local float4 idx
            int rrow = lf4 / 5, q = lf4 % 5;
            float* d = se + rrow * EMB_PAD + q * 4;
            d[0] = t.x; d[1] = t.y; d[2] = t.z; d[3] = t.w;
        }
    }
    __syncthreads();

    const int n = base + tid;
    const float* sWe1 = sw;        const float* sWe2 = sw + 300;
    const float* sWe3 = sw + 452;  const float* sWd1 = sw + 504;
    const float* sWd2 = sw + 556;  const float* sWd3 = sw + 708;
    const float* sbe1 = sw + 1008; const float* sbe2 = sw + 1023;
    const float* sbe3 = sw + 1033; const float* sbd1 = sw + 1038;
    const float* sbd2 = sw + 1048; const float* sbd3 = sw + 1063;

    if (n < N) {
        float x[20];
#pragma unroll
        for (int j = 0; j < 20; j++) x[j] = se[tid * EMB_PAD + j];

        float h1v[15];
#pragma unroll
        for (int i = 0; i < 15; i++) {
            float a = sbe1[i];
#pragma unroll
            for (int j = 0; j < 20; j++) a = fmaf(sWe1[i * 20 + j], x[j], a);
            h1v[i] = fmaxf(a, 0.f);
        }
        float h2v[10];
#pragma unroll
        for (int i = 0; i < 10; i++) {
            float a = sbe2[i];
#pragma unroll
            for (int j = 0; j < 15; j++) a = fmaf(sWe2[i * 15 + j], h1v[j], a);
            h2v[i] = fmaxf(a, 0.f);
        }
        float ev[5];
#pragma unroll
        for (int i = 0; i < 5; i++) {
            float a = sbe3[i];
#pragma unroll
            for (int j = 0; j < 10; j++) a = fmaf(sWe3[i * 10 + j], h2v[j], a);
            ev[i] = a;
        }
#pragma unroll
        for (int i = 0; i < 5; i++) enc_out[(size_t)n * 5 + i] = ev[i];

        float d1v[10];
#pragma unroll
        for (int i = 0; i < 10; i++) {
            float a = sbd1[i];
#pragma unroll
            for (int j = 0; j < 5; j++) a = fmaf(sWd1[i * 5 + j], ev[j], a);
            d1v[i] = fmaxf(a, 0.f);
        }
        float d2v[15];
#pragma unroll
        for (int i = 0; i < 15; i++) {
            float a = sbd2[i];
#pragma unroll
            for (int j = 0; j < 10; j++) a = fmaf(sWd2[i * 10 + j], d1v[j], a);
            d2v[i] = fmaxf(a, 0.f);
        }
        // decoded -> own row of se (each thread touches only its own row; the
        // earlier reads of this row were by this same thread, no sync needed)
#pragma unroll
        for (int i = 0; i < 20; i++) {
            float a = sbd3[i];
#pragma unroll
            for (int j = 0; j < 15; j++) a = fmaf(sWd3[i * 15 + j], d2v[j], a);
            se[tid * EMB_PAD + i] = a;
        }
    }
    __syncthreads();

    // coalesced float4 stores of decoded tile
#pragma unroll
    for (int i = 0; i < 5; i++) {
        long f4 = f4base + tid + i * MLP_BLK;
        if (f4 < f4total) {
            int lf4 = tid + i * MLP_BLK;
            int rrow = lf4 / 5, q = lf4 % 5;
            const float* s = se + rrow * EMB_PAD + q * 4;
            reinterpret_cast<float4*>(dec_out)[f4] =
                make_float4(s[0], s[1], s[2], s[3]);
        }
    }
}

// ---------------------------------------------------------------------------
extern "C" void kernel_launch(void* const* d_in, const int* in_sizes, int n_in,
                              void* d_out, int out_size)
{
    const float* features = (const float*)d_in[0];
    const int*   adj      = (const int*)d_in[1];
    const float* We1 = (const float*)d_in[2];  const float* be1 = (const float*)d_in[3];
    const float* We2 = (const float*)d_in[4];  const float* be2 = (const float*)d_in[5];
    const float* We3 = (const float*)d_in[6];  const float* be3 = (const float*)d_in[7];
    const float* Wd1 = (const float*)d_in[8];  const float* bd1 = (const float*)d_in[9];
    const float* Wd2 = (const float*)d_in[10]; const float* bd2 = (const float*)d_in[11];
    const float* Wd3 = (const float*)d_in[12]; const float* bd3 = (const float*)d_in[13];

    int N = in_sizes[0] / NODELEN;

    float* out = (float*)d_out;
    float* enc_out = out;                     // [N,5]
    float* dec_out = out + (size_t)N * 5;     // [N,20]
    float* emb_out = out + (size_t)N * 25;    // [N,20]

    int pack_blocks = (N * PADH + 255) / 256;
    pack_features_kernel<<<pack_blocks, 256>>>(features, N);

    int hop_blocks = (N + 7) / 8;   // one warp per node, 8 warps/block
    hop1_kernel<<<hop_blocks, 256>>>(adj, N);
    hop2_emb_kernel<<<hop_blocks, 256>>>(features, adj, emb_out, N);

    int mlp_blocks = (N + MLP_BLK - 1) / MLP_BLK;
    mlp_kernel<<<mlp_blocks, MLP_BLK>>>(emb_out,
                                        We1, be1, We2, be2, We3, be3,
                                        Wd1, bd1, Wd2, bd2, Wd3, bd3,
                                        enc_out, dec_out, N);
}

// round 5
// speedup vs baseline: 1.1213x; 1.1213x over previous
#include <cuda_runtime.h>
#include <cuda_fp16.h>

#define NODELEN 10
#define DEG 32
#define MAXN 200000
#define PADH 16   // halves per row: 32B = one sector, sector-aligned

// Allocation-free scratch: fp16 gather tables, one sector per row.
__device__ __half g_featH[(size_t)MAXN * PADH];
__device__ __half g_h1H[(size_t)MAXN * PADH];

// ---------------------------------------------------------------------------
// Pack: features [N,10] fp32 -> g_featH [N,16] fp16 (zero padded).
// ---------------------------------------------------------------------------
__global__ __launch_bounds__(256) void pack_features_kernel(
    const float* __restrict__ features, int N)
{
    int idx = blockIdx.x * blockDim.x + threadIdx.x;
    if (idx >= N * PADH) return;
    int n = idx >> 4;
    int k = idx & 15;
    float v = (k < NODELEN) ? features[(size_t)n * NODELEN + k] : 0.f;
    g_featH[idx] = __float2half_rn(v);
}

// ---------------------------------------------------------------------------
// Hop kernels: one warp per TWO nodes (16 independent gather LDGs in flight).
// Lane l: r = l>>3 (row-in-group 0..3), j = l&7 (dim pair). Each gathered row
// is 16 halves = 32B = ONE sector. Butterfly-reduce over r (xor 8,16).
// After reduction every lane holds full 32-row sums for its j, both nodes.
// ---------------------------------------------------------------------------
__global__ __launch_bounds__(256) void hop1_kernel(
    const int* __restrict__ adj, int N)
{
    int w    = (blockIdx.x * blockDim.x + threadIdx.x) >> 5;
    int lane = threadIdx.x & 31;
    int n0 = 2 * w, n1 = 2 * w + 1;
    if (n0 >= N) return;
    bool has1 = (n1 < N);

    int nb0 = adj[(size_t)n0 * DEG + lane];
    int nb1 = has1 ? adj[(size_t)n1 * DEG + lane] : nb0;

    int r = lane >> 3, j = lane & 7;
    float2 a0 = make_float2(0.f, 0.f), a1 = make_float2(0.f, 0.f);
#pragma unroll
    for (int i = 0; i < 8; i++) {
        int m0 = __shfl_sync(0xffffffffu, nb0, 4 * i + r);
        int m1 = __shfl_sync(0xffffffffu, nb1, 4 * i + r);
        float2 v0 = __half22float2(*reinterpret_cast<const __half2*>(
            g_featH + (size_t)m0 * PADH + 2 * j));
        float2 v1 = __half22float2(*reinterpret_cast<const __half2*>(
            g_featH + (size_t)m1 * PADH + 2 * j));
        a0.x += v0.x; a0.y += v0.y;
        a1.x += v1.x; a1.y += v1.y;
    }
#pragma unroll
    for (int off = 8; off < 32; off <<= 1) {
        a0.x += __shfl_xor_sync(0xffffffffu, a0.x, off);
        a0.y += __shfl_xor_sync(0xffffffffu, a0.y, off);
        a1.x += __shfl_xor_sync(0xffffffffu, a1.x, off);
        a1.y += __shfl_xor_sync(0xffffffffu, a1.y, off);
    }

    if (lane < 16) {
        int   node = (lane >> 3) ? n1 : n0;
        float2 s   = (lane >> 3) ? a1 : a0;
        if (node < N) {
            float vx = s.x * (1.f / 32.f);
            float vy = s.y * (1.f / 32.f);
            if (j == 0) vx = 0.f;            // h1[:,0] = 0
            *reinterpret_cast<__half2*>(g_h1H + (size_t)node * PADH + 2 * j) =
                __floats2half2_rn(vx, vy);
        }
    }
}

__global__ __launch_bounds__(256) void hop2_emb_kernel(
    const float* __restrict__ features, const int* __restrict__ adj,
    float* __restrict__ emb, int N)
{
    int w    = (blockIdx.x * blockDim.x + threadIdx.x) >> 5;
    int lane = threadIdx.x & 31;
    int n0 = 2 * w, n1 = 2 * w + 1;
    if (n0 >= N) return;
    bool has1 = (n1 < N);

    int nb0 = adj[(size_t)n0 * DEG + lane];
    int nb1 = has1 ? adj[(size_t)n1 * DEG + lane] : nb0;

    int r = lane >> 3, j = lane & 7;
    float2 a0 = make_float2(0.f, 0.f), a1 = make_float2(0.f, 0.f);
#pragma unroll
    for (int i = 0; i < 8; i++) {
        int m0 = __shfl_sync(0xffffffffu, nb0, 4 * i + r);
        int m1 = __shfl_sync(0xffffffffu, nb1, 4 * i + r);
        float2 v0 = __half22float2(*reinterpret_cast<const __half2*>(
            g_h1H + (size_t)m0 * PADH + 2 * j));
        float2 v1 = __half22float2(*reinterpret_cast<const __half2*>(
            g_h1H + (size_t)m1 * PADH + 2 * j));
        a0.x += v0.x; a0.y += v0.y;
        a1.x += v1.x; a1.y += v1.y;
    }
#pragma unroll
    for (int off = 8; off < 32; off <<= 1) {
        a0.x += __shfl_xor_sync(0xffffffffu, a0.x, off);
        a0.y += __shfl_xor_sync(0xffffffffu, a0.y, off);
        a1.x += __shfl_xor_sync(0xffffffffu, a1.x, off);
        a1.y += __shfl_xor_sync(0xffffffffu, a1.y, off);
    }

    // agg part: cols 10..19 (pairs j=0..4), col 10 zeroed
    if (lane < 16 && j < 5) {
        int    node = (lane >> 3) ? n1 : n0;
        float2 s    = (lane >> 3) ? a1 : a0;
        if (node < N) {
            float2 v;
            v.x = s.x * (1.f / 32.f);
            v.y = s.y * (1.f / 32.f);
            if (j == 0) v.x = 0.f;           // emb[:,NODELEN] = 0
            *reinterpret_cast<float2*>(emb + (size_t)node * 20 + 10 + 2 * j) = v;
        }
    }
    // self features: cols 0..9, col 0 zeroed (exact fp32 from input)
    if (lane >= 12) {
        int d, node;
        if (lane < 22) { d = lane - 12; node = n0; }
        else           { d = lane - 22; node = n1; }
        if (node < N) {
            float f = (d == 0) ? 0.f : features[(size_t)node * NODELEN + d];
            emb[(size_t)node * 20 + d] = f;
        }
    }
}

// ---------------------------------------------------------------------------
// MLP autoencoder: each thread processes TWO nodes packed into f32x2 lanes,
// using sm_103a packed fma.rn.f32x2 (FFMA2). Weights stored DUPLICATED in
// shared memory so an 8-byte LDS yields (w,w) with no pack instruction.
// ---------------------------------------------------------------------------
#define MLP_BLK 128
#define MLP_TILE (2 * MLP_BLK)   // 256 nodes per block
#define EMB_PAD 21               // odd stride -> conflict-free LDS

typedef unsigned long long u64;

__device__ __forceinline__ u64 pk2(float lo, float hi) {
    u64 r; asm("mov.b64 %0,{%1,%2};" : "=l"(r) : "f"(lo), "f"(hi)); return r;
}
__device__ __forceinline__ void up2(u64 v, float& lo, float& hi) {
    asm("mov.b64 {%0,%1},%2;" : "=f"(lo), "=f"(hi) : "l"(v));
}
__device__ __forceinline__ u64 fma2(u64 a, u64 b, u64 c) {
    u64 d; asm("fma.rn.f32x2 %0,%1,%2,%3;" : "=l"(d) : "l"(a), "l"(b), "l"(c));
    return d;
}
__device__ __forceinline__ u64 relu2(u64 v) {
    float lo, hi; up2(v, lo, hi);
    return pk2(fmaxf(lo, 0.f), fmaxf(hi, 0.f));
}

__global__ __launch_bounds__(MLP_BLK) void mlp_kernel(
    const float* __restrict__ emb,
    const float* __restrict__ We1, const float* __restrict__ be1,
    const float* __restrict__ We2, const float* __restrict__ be2,
    const float* __restrict__ We3, const float* __restrict__ be3,
    const float* __restrict__ Wd1, const float* __restrict__ bd1,
    const float* __restrict__ Wd2, const float* __restrict__ bd2,
    const float* __restrict__ Wd3, const float* __restrict__ bd3,
    float* __restrict__ enc_out, float* __restrict__ dec_out, int N)
{
    __shared__ __align__(16) float sw[2150];          // duplicated weights
    __shared__ float se[MLP_TILE * EMB_PAD];          // emb / decoded tile

    const int tid = threadIdx.x;
    {
        const float* srcs[12] = {We1, We2, We3, Wd1, Wd2, Wd3,
                                 be1, be2, be3, bd1, bd2, bd3};
        const int off[12] = {0, 600, 900, 1000, 1100, 1400,
                             2000, 2030, 2050, 2060, 2080, 2110};
        const int sz[12]  = {300, 150, 50, 50, 150, 300,
                             15, 10, 5, 10, 15, 20};
#pragma unroll
        for (int a = 0; a < 12; a++)
            for (int k = tid; k < sz[a]; k += MLP_BLK) {
                float v = srcs[a][k];
                sw[off[a] + 2 * k]     = v;
                sw[off[a] + 2 * k + 1] = v;
            }
    }

    // stage emb tile: coalesced float4 loads, OOB rows zeroed
    const int  base    = blockIdx.x * MLP_TILE;
    const long f4base  = (long)base * 5;
    const long f4total = (long)N * 5;
#pragma unroll
    for (int i = 0; i < 10; i++) {
        int  lf4 = tid + i * MLP_BLK;                 // 0..1279
        long f4  = f4base + lf4;
        float4 t = (f4 < f4total) ? reinterpret_cast<const float4*>(emb)[f4]
                                  : make_float4(0.f, 0.f, 0.f, 0.f);
        int rr = lf4 / 5, q = lf4 % 5;
        float* d = se + rr * EMB_PAD + q * 4;
        d[0] = t.x; d[1] = t.y; d[2] = t.z; d[3] = t.w;
    }
    __syncthreads();

    const int n0 = base + tid;
    const int n1 = base + MLP_BLK + tid;

    // duplicated-weight views (u64 index = float offset / 2)
    const u64* wWe1 = (const u64*)(sw);          // [15][20]
    const u64* wWe2 = (const u64*)(sw) + 300;    // [10][15]
    const u64* wWe3 = (const u64*)(sw) + 450;    // [5][10]
    const u64* wWd1 = (const u64*)(sw) + 500;    // [10][5]
    const u64* wWd2 = (const u64*)(sw) + 550;    // [15][10]
    const u64* wWd3 = (const u64*)(sw) + 700;    // [20][15]
    const u64* vbe1 = (const u64*)(sw) + 1000;
    const u64* vbe2 = (const u64*)(sw) + 1015;
    const u64* vbe3 = (const u64*)(sw) + 1025;
    const u64* vbd1 = (const u64*)(sw) + 1030;
    const u64* vbd2 = (const u64*)(sw) + 1040;
    const u64* vbd3 = (const u64*)(sw) + 1055;

    // pack activations: lane-wise (node0, node1)
    u64 x[20];
    {
        const float* r0 = se + tid * EMB_PAD;
        const float* r1 = se + (tid + MLP_BLK) * EMB_PAD;
#pragma unroll
        for (int jx = 0; jx < 20; jx++) x[jx] = pk2(r0[jx], r1[jx]);
    }

    u64 h1v[15];
#pragma unroll
    for (int i = 0; i < 15; i++) {
        u64 a = vbe1[i];
#pragma unroll
        for (int jx = 0; jx < 20; jx++) a = fma2(wWe1[i * 20 + jx], x[jx], a);
        h1v[i] = relu2(a);
    }
    u64 h2v[10];
#pragma unroll
    for (int i = 0; i < 10; i++) {
        u64 a = vbe2[i];
#pragma unroll
        for (int jx = 0; jx < 15; jx++) a = fma2(wWe2[i * 15 + jx], h1v[jx], a);
        h2v[i] = relu2(a);
    }
    u64 ev[5];
#pragma unroll
    for (int i = 0; i < 5; i++) {
        u64 a = vbe3[i];
#pragma unroll
        for (int jx = 0; jx < 10; jx++) a = fma2(wWe3[i * 10 + jx], h2v[jx], a);
        ev[i] = a;                                    // encoded: no relu
    }
#pragma unroll
    for (int i = 0; i < 5; i++) {
        float e0, e1; up2(ev[i], e0, e1);
        if (n0 < N) enc_out[(size_t)n0 * 5 + i] = e0;
        if (n1 < N) enc_out[(size_t)n1 * 5 + i] = e1;
    }

    u64 d1v[10];
#pragma unroll
    for (int i = 0; i < 10; i++) {
        u64 a = vbd1[i];
#pragma unroll
        for (int jx = 0; jx < 5; jx++) a = fma2(wWd1[i * 5 + jx], ev[jx], a);
        d1v[i] = relu2(a);
    }
    u64 d2v[15];
#pragma unroll
    for (int i = 0; i < 15; i++) {
        u64 a = vbd2[i];
#pragma unroll
        for (int jx = 0; jx < 10; jx++) a = fma2(wWd2[i * 10 + jx], d1v[jx], a);
        d2v[i] = relu2(a);
    }
    // decoded -> own two rows of se (only this thread ever touches them)
#pragma unroll
    for (int i = 0; i < 20; i++) {
        u64 a = vbd3[i];
#pragma unroll
        for (int jx = 0; jx < 15; jx++) a = fma2(wWd3[i * 15 + jx], d2v[jx], a);
        float d0, d1; up2(a, d0, d1);
        se[tid * EMB_PAD + i]             = d0;
        se[(tid + MLP_BLK) * EMB_PAD + i] = d1;
    }
    __syncthreads();

    // coalesced float4 export of decoded tile
#pragma unroll
    for (int i = 0; i < 10; i++) {
        int  lf4 = tid + i * MLP_BLK;
        long f4  = f4base + lf4;
        if (f4 < f4total) {
            int rr = lf4 / 5, q = lf4 % 5;
            const float* s = se + rr * EMB_PAD + q * 4;
            reinterpret_cast<float4*>(dec_out)[f4] =
                make_float4(s[0], s[1], s[2], s[3]);
        }
    }
}

// ---------------------------------------------------------------------------
extern "C" void kernel_launch(void* const* d_in, const int* in_sizes, int n_in,
                              void* d_out, int out_size)
{
    const float* features = (const float*)d_in[0];
    const int*   adj      = (const int*)d_in[1];
    const float* We1 = (const float*)d_in[2];  const float* be1 = (const float*)d_in[3];
    const float* We2 = (const float*)d_in[4];  const float* be2 = (const float*)d_in[5];
    const float* We3 = (const float*)d_in[6];  const float* be3 = (const float*)d_in[7];
    const float* Wd1 = (const float*)d_in[8];  const float* bd1 = (const float*)d_in[9];
    const float* Wd2 = (const float*)d_in[10]; const float* bd2 = (const float*)d_in[11];
    const float* Wd3 = (const float*)d_in[12]; const float* bd3 = (const float*)d_in[13];

    int N = in_sizes[0] / NODELEN;

    float* out = (float*)d_out;
    float* enc_out = out;                     // [N,5]
    float* dec_out = out + (size_t)N * 5;     // [N,20]
    float* emb_out = out + (size_t)N * 25;    // [N,20]

    int pack_blocks = (N * PADH + 255) / 256;
    pack_features_kernel<<<pack_blocks, 256>>>(features, N);

    // one warp per 2 nodes, 8 warps/block -> 16 nodes/block
    int hop_blocks = (N + 15) / 16;
    hop1_kernel<<<hop_blocks, 256>>>(adj, N);
    hop2_emb_kernel<<<hop_blocks, 256>>>(features, adj, emb_out, N);

    int mlp_blocks = (N + MLP_TILE - 1) / MLP_TILE;
    mlp_kernel<<<mlp_blocks, MLP_BLK>>>(emb_out,
                                        We1, be1, We2, be2, We3, be3,
                                        Wd1, bd1, Wd2, bd2, Wd3, bd3,
                                        enc_out, dec_out, N);
}